// round 10
// baseline (speedup 1.0000x reference)
#include <cuda_runtime.h>
#include <cstdint>

// Masked row-wise cumsum: out[r,:] = cumsum(x[r,:] * mask[r,:])
// x: f32 [4096, 32768]; mask: 4-byte 0/1 words on the wire (byte fallback
// kept); out: f32 [4096, 32768].
//
// PERSISTENT single-wave version of the R8 champion: grid = #SMs * 4, each
// CTA owns a CONTIGUOUS span of rows. Rows are contiguous in memory, so the
// 2-stage cp.async pipeline streams unbroken across row boundaries: one
// prologue per CTA, no inter-row pipeline drains, no wave transitions, no
// ragged last wave. Carry resets every (n_cols/CHUNK) chunks.

#ifndef CUMSUM_N
#define CUMSUM_N 32768
#endif

#define TPB    512
#define VEC    4
#define CHUNK  (TPB * VEC)          // 2048 elements
#define NWARP  (TPB / 32)           // 16
#define STAGES 2
#define CPR    (CUMSUM_N / CHUNK)   // 16 chunks per row

#define XSTAGE_B (TPB * 16)         // 8192 B per x stage
#define MSTAGE_B (TPB * 16)         // 8192 B per mask stage (word mode)

__device__ __forceinline__ unsigned smem_u32(const void* p)
{
    unsigned a;
    asm("{ .reg .u64 t; cvta.to.shared.u64 t, %1; cvt.u32.u64 %0, t; }"
        : "=r"(a) : "l"(p));
    return a;
}

__device__ __forceinline__ void cp_async16(unsigned dst, const void* src)
{
    asm volatile("cp.async.cg.shared.global [%0], [%1], 16;"
                 :: "r"(dst), "l"(src) : "memory");
}

__device__ __forceinline__ void cp_async4(unsigned dst, const void* src)
{
    asm volatile("cp.async.ca.shared.global [%0], [%1], 4;"
                 :: "r"(dst), "l"(src) : "memory");
}

__device__ __forceinline__ void cp_commit()
{
    asm volatile("cp.async.commit_group;" ::: "memory");
}

__device__ __forceinline__ void cp_wait1()
{
    asm volatile("cp.async.wait_group 1;" ::: "memory");
}

__global__ __launch_bounds__(TPB, 4)
void masked_cumsum_persist_kernel(const float* __restrict__ x,
                                  const void* __restrict__ mask,
                                  float* __restrict__ out,
                                  int n_rows)
{
    const int nb = gridDim.x;
    const int b  = blockIdx.x;

    // contiguous row span for this CTA
    const int base_rows = n_rows / nb;
    const int rem       = n_rows - base_rows * nb;
    const int start_row = b * base_rows + (b < rem ? b : rem);
    const int count     = base_rows + (b < rem ? 1 : 0);

    const size_t base = (size_t)start_row * (size_t)CUMSUM_N;
    const int nch = count * CPR;            // total chunks, contiguous stream

    const int tid  = threadIdx.x;
    const int lane = tid & 31;
    const int wid  = tid >> 5;

    // --- per-warp mask dtype detection (deterministic, no barrier) ---
    const unsigned probe = ((const unsigned*)mask)[lane];
    const bool clean = (probe == 0u) | (probe == 1u) | (probe == 0x3F800000u);
    const bool word_mode = __all_sync(0xffffffffu, clean);

    __shared__ float4 s_x[STAGES][TPB];      // 16 KB
    __shared__ uint4  s_m[STAGES][TPB];      // 16 KB (byte mode uses 2 KB/stage)
    __shared__ float  s_warp[2][NWARP];

    const unsigned sx_t  = smem_u32(&s_x[0][tid]);
    const unsigned sm_t  = smem_u32(&s_m[0][tid]);
    const unsigned smb_t = smem_u32(&s_m[0][0]) + tid * 4;

    // running global pointers (strength-reduced), continuous across rows
    const float*    xg   = x + base + (size_t)tid * VEC;
    const unsigned* mg_w = (const unsigned*)mask + base + (size_t)tid * VEC;
    const uint8_t*  mg_b = (const uint8_t*)mask + base + (size_t)tid * VEC;
    float*          og   = out + base + (size_t)tid * VEC;

    // ---- prologue: prefetch chunks 0..1 (once per CTA for the whole run) ----
    #pragma unroll
    for (int s = 0; s < STAGES; s++) {
        cp_async16(sx_t + s * XSTAGE_B, xg);
        if (word_mode) cp_async16(sm_t + s * MSTAGE_B, mg_w);
        else           cp_async4(smb_t + s * MSTAGE_B, mg_b);
        cp_commit();
        xg   += CHUNK;
        mg_w += CHUNK;
        mg_b += CHUNK;
    }

    float carry = 0.0f;
    int p  = 0;   // consume stage
    int pp = 0;   // ping-pong for warp totals

    #pragma unroll 1
    for (int c = 0; c < nch; c++) {
        if ((c & (CPR - 1)) == 0) carry = 0.0f;   // new row starts

        cp_wait1();   // chunk c's slices have landed

        const float4 xv = s_x[p][tid];

        float v0, v1, v2, v3;
        if (word_mode) {
            const uint4 mv = s_m[p][tid];
            v0 = mv.x ? xv.x : 0.f;
            v1 = mv.y ? xv.y : 0.f;
            v2 = mv.z ? xv.z : 0.f;
            v3 = mv.w ? xv.w : 0.f;
        } else {
            const unsigned mv =
                *reinterpret_cast<const unsigned*>(
                    reinterpret_cast<const uint8_t*>(&s_m[p][0]) + tid * 4);
            v0 = (mv & 0x000000FFu) ? xv.x : 0.f;
            v1 = (mv & 0x0000FF00u) ? xv.y : 0.f;
            v2 = (mv & 0x00FF0000u) ? xv.z : 0.f;
            v3 = (mv & 0xFF000000u) ? xv.w : 0.f;
        }

        // ---- refill stage p with chunk c+STAGES ----
        if (c + STAGES < nch) {
            cp_async16(sx_t + p * XSTAGE_B, xg);
            if (word_mode) cp_async16(sm_t + p * MSTAGE_B, mg_w);
            else           cp_async4(smb_t + p * MSTAGE_B, mg_b);
            xg   += CHUNK;
            mg_w += CHUNK;
            mg_b += CHUNK;
        }
        cp_commit();   // uniform group accounting

        // ---- thread-local inclusive scan of 4 ----
        const float s0 = v0;
        const float s1 = s0 + v1;
        const float s2 = s1 + v2;
        const float s3 = s2 + v3;

        // ---- warp inclusive scan of per-thread totals ----
        float t = s3;
        #pragma unroll
        for (int d = 1; d < 32; d <<= 1) {
            float nv = __shfl_up_sync(0xffffffffu, t, d);
            if (lane >= d) t += nv;
        }
        const float thread_excl = t - s3;

        if (lane == 31) s_warp[pp][wid] = t;
        __syncthreads();                      // the ONLY barrier per chunk

        // ---- every warp redundantly scans the 16 warp totals ----
        float wincl = (lane < NWARP) ? s_warp[pp][lane] : 0.f;
        #pragma unroll
        for (int d = 1; d < NWARP; d <<= 1) {
            float nv = __shfl_up_sync(0xffffffffu, wincl, d);
            if (lane >= d) wincl += nv;
        }
        const float warp_excl = (wid == 0)
            ? 0.f
            : __shfl_sync(0xffffffffu, wincl, wid - 1);
        const float block_tot = __shfl_sync(0xffffffffu, wincl, NWARP - 1);

        const float offv = carry + warp_excl + thread_excl;

        float4 o;
        o.x = s0 + offv;
        o.y = s1 + offv;
        o.z = s2 + offv;
        o.w = s3 + offv;
        __stcs(reinterpret_cast<float4*>(og), o);
        og += CHUNK;

        carry += block_tot;
        p  ^= 1;
        pp ^= 1;
    }
}

extern "C" void kernel_launch(void* const* d_in, const int* in_sizes, int n_in,
                              void* d_out, int out_size)
{
    const float* x    = (const float*)d_in[0];
    const void*  mask = d_in[1];
    float*       out  = (float*)d_out;

    const int n_rows = in_sizes[0] / CUMSUM_N;   // 4096

    int sm_count = 148;
    cudaDeviceGetAttribute(&sm_count, cudaDevAttrMultiProcessorCount, 0);
    int grid = sm_count * 4;                     // one full wave at 4 CTAs/SM
    if (grid > n_rows) grid = n_rows;

    masked_cumsum_persist_kernel<<<grid, TPB>>>(x, mask, out, n_rows);
}

// round 11
// speedup vs baseline: 1.1330x; 1.1330x over previous
#include <cuda_runtime.h>
#include <cstdint>

// Masked row-wise cumsum: out[r,:] = cumsum(x[r,:] * mask[r,:])
// x: f32 [4096, 32768]; mask: 4-byte 0/1 words on the wire (byte fallback
// kept); out: f32 [4096, 32768].
//
// R8 champion (1 CTA/row, 512 thr, cp.async SMEM staging, 4 CTAs/SM) with
// PAIRED CHUNKS: one barrier + ONE 32-lane shfl scan resolves the inter-warp
// prefixes of TWO 2048-elem chunks (lanes 0-15 = chunk A warp totals,
// 16-31 = chunk B). Barriers per row: 16 -> 8. 3 single-chunk cp.async
// stages (48KB dynamic smem), wait_group 1 per pair, refills issued
// pre-barrier right after values are consumed into registers.

#ifndef CUMSUM_N
#define CUMSUM_N 32768
#endif

#define TPB    512
#define VEC    4
#define CHUNK  (TPB * VEC)          // 2048 elements
#define NWARP  (TPB / 32)           // 16
#define STAGES 3
#define CPR    (CUMSUM_N / CHUNK)   // 16 chunks per row
#define NPAIR  (CPR / 2)            // 8 pair-iterations per row

#define STAGE_B   (TPB * 16)        // 8192 B per stage per operand
#define SM_X_OFF  0
#define SM_M_OFF  (STAGES * STAGE_B)             // 24576
#define SM_W_OFF  (2 * STAGES * STAGE_B)         // 49152
#define SMEM_TOTAL (SM_W_OFF + 2 * 32 * 4)       // + 2 ping-pong warp arrays

__device__ __forceinline__ unsigned smem_u32(const void* p)
{
    unsigned a;
    asm("{ .reg .u64 t; cvta.to.shared.u64 t, %1; cvt.u32.u64 %0, t; }"
        : "=r"(a) : "l"(p));
    return a;
}

__device__ __forceinline__ void cp_async16(unsigned dst, const void* src)
{
    asm volatile("cp.async.cg.shared.global [%0], [%1], 16;"
                 :: "r"(dst), "l"(src) : "memory");
}

__device__ __forceinline__ void cp_async4(unsigned dst, const void* src)
{
    asm volatile("cp.async.ca.shared.global [%0], [%1], 4;"
                 :: "r"(dst), "l"(src) : "memory");
}

__device__ __forceinline__ void cp_commit()
{
    asm volatile("cp.async.commit_group;" ::: "memory");
}

__device__ __forceinline__ void cp_wait1()
{
    asm volatile("cp.async.wait_group 1;" ::: "memory");
}

// ---- masked load of one chunk slice from stage s ----
template<bool WORD>
__device__ __forceinline__ void load_vals(const char* sm, int s, int tid,
                                          float& v0, float& v1, float& v2, float& v3)
{
    const float4 xv = reinterpret_cast<const float4*>(sm + SM_X_OFF + s * STAGE_B)[tid];
    if (WORD) {
        const uint4 mv = reinterpret_cast<const uint4*>(sm + SM_M_OFF + s * STAGE_B)[tid];
        v0 = mv.x ? xv.x : 0.f;
        v1 = mv.y ? xv.y : 0.f;
        v2 = mv.z ? xv.z : 0.f;
        v3 = mv.w ? xv.w : 0.f;
    } else {
        const unsigned mv =
            reinterpret_cast<const unsigned*>(sm + SM_M_OFF + s * STAGE_B)[tid];
        v0 = (mv & 0x000000FFu) ? xv.x : 0.f;
        v1 = (mv & 0x0000FF00u) ? xv.y : 0.f;
        v2 = (mv & 0x00FF0000u) ? xv.z : 0.f;
        v3 = (mv & 0xFF000000u) ? xv.w : 0.f;
    }
}

template<bool WORD>
__device__ __forceinline__ void run(const float* __restrict__ x,
                                    const void* __restrict__ mask,
                                    float* __restrict__ out,
                                    char* sm)
{
    const int row  = blockIdx.x;
    const size_t base = (size_t)row * (size_t)CUMSUM_N;

    const int tid  = threadIdx.x;
    const int lane = tid & 31;
    const int wid  = tid >> 5;

    float* s_warp = reinterpret_cast<float*>(sm + SM_W_OFF);   // [2][32]

    const unsigned sx_t  = smem_u32(sm + SM_X_OFF) + tid * 16;
    const unsigned sm_t  = smem_u32(sm + SM_M_OFF) + (WORD ? tid * 16 : tid * 4);

    const float*    xg = x + base + (size_t)tid * VEC;
    const unsigned* mg_w = (const unsigned*)mask + base + (size_t)tid * VEC;
    const uint8_t*  mg_b = (const uint8_t*)mask + base + (size_t)tid * VEC;
    float*          og = out + base + (size_t)tid * VEC;

    // ---- prologue: prefetch chunks 0..2 ----
    #pragma unroll
    for (int s = 0; s < STAGES; s++) {
        cp_async16(sx_t + s * STAGE_B, xg);
        if (WORD) cp_async16(sm_t + s * STAGE_B, mg_w);
        else      cp_async4(sm_t + s * STAGE_B, mg_b);
        cp_commit();
        xg += CHUNK; mg_w += CHUNK; mg_b += CHUNK;
    }

    float carry = 0.0f;
    int sA = 0;       // stage holding chunk 2k; chunk 2k+1 is in (sA+1)%3
    int pp = 0;

    #pragma unroll 1
    for (int k = 0; k < NPAIR; k++) {
        const int c  = 2 * k;
        const int sB = (sA == STAGES - 1) ? 0 : sA + 1;

        cp_wait1();   // chunks c and c+1 have landed (own slices)

        // ---- chunk A: local + warp scan ----
        float a0, a1, a2, a3;
        load_vals<WORD>(sm, sA, tid, a0, a1, a2, a3);
        const float sa0 = a0, sa1 = sa0 + a1, sa2 = sa1 + a2, sa3 = sa2 + a3;
        float tA = sa3;
        #pragma unroll
        for (int d = 1; d < 32; d <<= 1) {
            float nv = __shfl_up_sync(0xffffffffu, tA, d);
            if (lane >= d) tA += nv;
        }
        const float thread_exclA = tA - sa3;
        if (lane == 31) s_warp[pp * 32 + wid] = tA;

        // ---- chunk B: local + warp scan ----
        float b0, b1, b2, b3;
        load_vals<WORD>(sm, sB, tid, b0, b1, b2, b3);
        const float sb0 = b0, sb1 = sb0 + b1, sb2 = sb1 + b2, sb3 = sb2 + b3;
        float tB = sb3;
        #pragma unroll
        for (int d = 1; d < 32; d <<= 1) {
            float nv = __shfl_up_sync(0xffffffffu, tB, d);
            if (lane >= d) tB += nv;
        }
        const float thread_exclB = tB - sb3;
        if (lane == 31) s_warp[pp * 32 + 16 + wid] = tB;

        // ---- refill stages sA, sB with chunks c+3, c+4 (values consumed) ----
        if (c + 3 < CPR) {
            cp_async16(sx_t + sA * STAGE_B, xg);
            if (WORD) cp_async16(sm_t + sA * STAGE_B, mg_w);
            else      cp_async4(sm_t + sA * STAGE_B, mg_b);
            xg += CHUNK; mg_w += CHUNK; mg_b += CHUNK;
        }
        cp_commit();
        if (c + 4 < CPR) {
            cp_async16(sx_t + sB * STAGE_B, xg);
            if (WORD) cp_async16(sm_t + sB * STAGE_B, mg_w);
            else      cp_async4(sm_t + sB * STAGE_B, mg_b);
            xg += CHUNK; mg_w += CHUNK; mg_b += CHUNK;
        }
        cp_commit();

        __syncthreads();              // the ONLY barrier per PAIR of chunks

        // ---- one 32-lane scan resolves both chunks' warp prefixes ----
        float wincl = s_warp[pp * 32 + lane];
        #pragma unroll
        for (int d = 1; d < 32; d <<= 1) {
            float nv = __shfl_up_sync(0xffffffffu, wincl, d);
            if (lane >= d) wincl += nv;
        }
        const float exclA = (wid == 0)
            ? 0.f
            : __shfl_sync(0xffffffffu, wincl, wid - 1);
        const float exclB = __shfl_sync(0xffffffffu, wincl, 15 + wid);
        const float pair_tot = __shfl_sync(0xffffffffu, wincl, 31);

        const float offA = carry + exclA + thread_exclA;
        const float offB = carry + exclB + thread_exclB;

        float4 oA;
        oA.x = sa0 + offA; oA.y = sa1 + offA;
        oA.z = sa2 + offA; oA.w = sa3 + offA;
        __stcs(reinterpret_cast<float4*>(og), oA);

        float4 oB;
        oB.x = sb0 + offB; oB.y = sb1 + offB;
        oB.z = sb2 + offB; oB.w = sb3 + offB;
        __stcs(reinterpret_cast<float4*>(og + CHUNK), oB);

        og += 2 * CHUNK;
        carry += pair_tot;
        sA = (sB == STAGES - 1) ? 0 : sB + 1;
        pp ^= 1;
    }
}

__global__ __launch_bounds__(TPB, 4)
void masked_cumsum_pair_kernel(const float* __restrict__ x,
                               const void* __restrict__ mask,
                               float* __restrict__ out)
{
    extern __shared__ char sm[];
    const int lane = threadIdx.x & 31;

    // per-warp mask dtype detection (deterministic, no barrier)
    const unsigned probe = ((const unsigned*)mask)[lane];
    const bool clean = (probe == 0u) | (probe == 1u) | (probe == 0x3F800000u);
    const bool word_mode = __all_sync(0xffffffffu, clean);

    if (word_mode) run<true >(x, mask, out, sm);
    else           run<false>(x, mask, out, sm);
}

extern "C" void kernel_launch(void* const* d_in, const int* in_sizes, int n_in,
                              void* d_out, int out_size)
{
    const float* x    = (const float*)d_in[0];
    const void*  mask = d_in[1];
    float*       out  = (float*)d_out;

    const int n_rows = in_sizes[0] / CUMSUM_N;   // 4096

    static bool attr_set = false;
    if (!attr_set) {
        cudaFuncSetAttribute(masked_cumsum_pair_kernel,
                             cudaFuncAttributeMaxDynamicSharedMemorySize,
                             SMEM_TOTAL);
        attr_set = true;
    }

    masked_cumsum_pair_kernel<<<n_rows, TPB, SMEM_TOTAL>>>(x, mask, out);
}

// round 12
// speedup vs baseline: 1.1489x; 1.0140x over previous
#include <cuda_runtime.h>
#include <cstdint>

// Masked row-wise cumsum: out[r,:] = cumsum(x[r,:] * mask[r,:])
// x: f32 [4096, 32768]; mask: 4-byte 0/1 words on the wire (byte fallback
// kept); out: f32 [4096, 32768].
//
// R11 champion (1 CTA/row, 512 thr, 4 CTAs/SM, 3-stage cp.async staging,
// paired chunks, ONE barrier + ONE 32-lane scan per 4096 elems) with
// scheduling polish: each stage's refill is issued IMMEDIATELY after its
// values are consumed into registers (before that chunk's shfl chain), and
// chunk A's store is issued before chunk B's offset math. We are at the
// LTS fabric ceiling (~6.7 TB/s path-independent); floor ~228-230us.

#ifndef CUMSUM_N
#define CUMSUM_N 32768
#endif

#define TPB    512
#define VEC    4
#define CHUNK  (TPB * VEC)          // 2048 elements
#define NWARP  (TPB / 32)           // 16
#define STAGES 3
#define CPR    (CUMSUM_N / CHUNK)   // 16 chunks per row
#define NPAIR  (CPR / 2)            // 8 pair-iterations per row

#define STAGE_B   (TPB * 16)        // 8192 B per stage per operand
#define SM_X_OFF  0
#define SM_M_OFF  (STAGES * STAGE_B)             // 24576
#define SM_W_OFF  (2 * STAGES * STAGE_B)         // 49152
#define SMEM_TOTAL (SM_W_OFF + 2 * 32 * 4)

__device__ __forceinline__ unsigned smem_u32(const void* p)
{
    unsigned a;
    asm("{ .reg .u64 t; cvta.to.shared.u64 t, %1; cvt.u32.u64 %0, t; }"
        : "=r"(a) : "l"(p));
    return a;
}

__device__ __forceinline__ void cp_async16(unsigned dst, const void* src)
{
    asm volatile("cp.async.cg.shared.global [%0], [%1], 16;"
                 :: "r"(dst), "l"(src) : "memory");
}

__device__ __forceinline__ void cp_async4(unsigned dst, const void* src)
{
    asm volatile("cp.async.ca.shared.global [%0], [%1], 4;"
                 :: "r"(dst), "l"(src) : "memory");
}

__device__ __forceinline__ void cp_commit()
{
    asm volatile("cp.async.commit_group;" ::: "memory");
}

__device__ __forceinline__ void cp_wait1()
{
    asm volatile("cp.async.wait_group 1;" ::: "memory");
}

template<bool WORD>
__device__ __forceinline__ void load_vals(const char* sm, int s, int tid,
                                          float& v0, float& v1, float& v2, float& v3)
{
    const float4 xv = reinterpret_cast<const float4*>(sm + SM_X_OFF + s * STAGE_B)[tid];
    if (WORD) {
        const uint4 mv = reinterpret_cast<const uint4*>(sm + SM_M_OFF + s * STAGE_B)[tid];
        v0 = mv.x ? xv.x : 0.f;
        v1 = mv.y ? xv.y : 0.f;
        v2 = mv.z ? xv.z : 0.f;
        v3 = mv.w ? xv.w : 0.f;
    } else {
        const unsigned mv =
            reinterpret_cast<const unsigned*>(sm + SM_M_OFF + s * STAGE_B)[tid];
        v0 = (mv & 0x000000FFu) ? xv.x : 0.f;
        v1 = (mv & 0x0000FF00u) ? xv.y : 0.f;
        v2 = (mv & 0x00FF0000u) ? xv.z : 0.f;
        v3 = (mv & 0xFF000000u) ? xv.w : 0.f;
    }
}

template<bool WORD>
__device__ __forceinline__ void run(const float* __restrict__ x,
                                    const void* __restrict__ mask,
                                    float* __restrict__ out,
                                    char* sm)
{
    const int row  = blockIdx.x;
    const size_t base = (size_t)row * (size_t)CUMSUM_N;

    const int tid  = threadIdx.x;
    const int lane = tid & 31;
    const int wid  = tid >> 5;

    float* s_warp = reinterpret_cast<float*>(sm + SM_W_OFF);   // [2][32]

    const unsigned sx_t = smem_u32(sm + SM_X_OFF) + tid * 16;
    const unsigned sm_t = smem_u32(sm + SM_M_OFF) + (WORD ? tid * 16 : tid * 4);

    const float*    xg   = x + base + (size_t)tid * VEC;
    const unsigned* mg_w = (const unsigned*)mask + base + (size_t)tid * VEC;
    const uint8_t*  mg_b = (const uint8_t*)mask + base + (size_t)tid * VEC;
    float*          og   = out + base + (size_t)tid * VEC;

    // ---- prologue: prefetch chunks 0..2 ----
    #pragma unroll
    for (int s = 0; s < STAGES; s++) {
        cp_async16(sx_t + s * STAGE_B, xg);
        if (WORD) cp_async16(sm_t + s * STAGE_B, mg_w);
        else      cp_async4(sm_t + s * STAGE_B, mg_b);
        cp_commit();
        xg += CHUNK; mg_w += CHUNK; mg_b += CHUNK;
    }

    float carry = 0.0f;
    int sA = 0;
    int pp = 0;

    #pragma unroll 1
    for (int k = 0; k < NPAIR; k++) {
        const int c  = 2 * k;
        const int sB = (sA == STAGES - 1) ? 0 : sA + 1;

        cp_wait1();   // chunks c and c+1 have landed (own slices)

        // ---- chunk A: consume values, then refill its stage IMMEDIATELY ----
        float a0, a1, a2, a3;
        load_vals<WORD>(sm, sA, tid, a0, a1, a2, a3);
        if (c + 3 < CPR) {
            cp_async16(sx_t + sA * STAGE_B, xg);
            if (WORD) cp_async16(sm_t + sA * STAGE_B, mg_w);
            else      cp_async4(sm_t + sA * STAGE_B, mg_b);
            xg += CHUNK; mg_w += CHUNK; mg_b += CHUNK;
        }
        cp_commit();

        const float sa0 = a0, sa1 = sa0 + a1, sa2 = sa1 + a2, sa3 = sa2 + a3;
        float tA = sa3;
        #pragma unroll
        for (int d = 1; d < 32; d <<= 1) {
            float nv = __shfl_up_sync(0xffffffffu, tA, d);
            if (lane >= d) tA += nv;
        }
        const float thread_exclA = tA - sa3;
        if (lane == 31) s_warp[pp * 32 + wid] = tA;

        // ---- chunk B: consume values, refill its stage IMMEDIATELY ----
        float b0, b1, b2, b3;
        load_vals<WORD>(sm, sB, tid, b0, b1, b2, b3);
        if (c + 4 < CPR) {
            cp_async16(sx_t + sB * STAGE_B, xg);
            if (WORD) cp_async16(sm_t + sB * STAGE_B, mg_w);
            else      cp_async4(sm_t + sB * STAGE_B, mg_b);
            xg += CHUNK; mg_w += CHUNK; mg_b += CHUNK;
        }
        cp_commit();

        const float sb0 = b0, sb1 = sb0 + b1, sb2 = sb1 + b2, sb3 = sb2 + b3;
        float tB = sb3;
        #pragma unroll
        for (int d = 1; d < 32; d <<= 1) {
            float nv = __shfl_up_sync(0xffffffffu, tB, d);
            if (lane >= d) tB += nv;
        }
        const float thread_exclB = tB - sb3;
        if (lane == 31) s_warp[pp * 32 + 16 + wid] = tB;

        __syncthreads();              // the ONLY barrier per PAIR of chunks

        // ---- one 32-lane scan resolves both chunks' warp prefixes ----
        float wincl = s_warp[pp * 32 + lane];
        #pragma unroll
        for (int d = 1; d < 32; d <<= 1) {
            float nv = __shfl_up_sync(0xffffffffu, wincl, d);
            if (lane >= d) wincl += nv;
        }
        const float exclA = (wid == 0)
            ? 0.f
            : __shfl_sync(0xffffffffu, wincl, wid - 1);

        // store A as early as possible
        const float offA = carry + exclA + thread_exclA;
        float4 oA;
        oA.x = sa0 + offA; oA.y = sa1 + offA;
        oA.z = sa2 + offA; oA.w = sa3 + offA;
        __stcs(reinterpret_cast<float4*>(og), oA);

        const float exclB    = __shfl_sync(0xffffffffu, wincl, 15 + wid);
        const float pair_tot = __shfl_sync(0xffffffffu, wincl, 31);

        const float offB = carry + exclB + thread_exclB;
        float4 oB;
        oB.x = sb0 + offB; oB.y = sb1 + offB;
        oB.z = sb2 + offB; oB.w = sb3 + offB;
        __stcs(reinterpret_cast<float4*>(og + CHUNK), oB);

        og += 2 * CHUNK;
        carry += pair_tot;
        sA = (sB == STAGES - 1) ? 0 : sB + 1;
        pp ^= 1;
    }
}

__global__ __launch_bounds__(TPB, 4)
void masked_cumsum_pair_kernel(const float* __restrict__ x,
                               const void* __restrict__ mask,
                               float* __restrict__ out)
{
    extern __shared__ char sm[];
    const int lane = threadIdx.x & 31;

    // per-warp mask dtype detection (deterministic, no barrier)
    const unsigned probe = ((const unsigned*)mask)[lane];
    const bool clean = (probe == 0u) | (probe == 1u) | (probe == 0x3F800000u);
    const bool word_mode = __all_sync(0xffffffffu, clean);

    if (word_mode) run<true >(x, mask, out, sm);
    else           run<false>(x, mask, out, sm);
}

extern "C" void kernel_launch(void* const* d_in, const int* in_sizes, int n_in,
                              void* d_out, int out_size)
{
    const float* x    = (const float*)d_in[0];
    const void*  mask = d_in[1];
    float*       out  = (float*)d_out;

    const int n_rows = in_sizes[0] / CUMSUM_N;   // 4096

    static bool attr_set = false;
    if (!attr_set) {
        cudaFuncSetAttribute(masked_cumsum_pair_kernel,
                             cudaFuncAttributeMaxDynamicSharedMemorySize,
                             SMEM_TOTAL);
        attr_set = true;
    }

    masked_cumsum_pair_kernel<<<n_rows, TPB, SMEM_TOTAL>>>(x, mask, out);
}